// round 16
// baseline (speedup 1.0000x reference)
#include <cuda_runtime.h>
#include <cstdint>

#define HID   16
#define INS   64
#define SEQT  12
#define RW    16           // rows per warp
#define NWARP 4
#define TILE_B (RW * NWARP)
#define XSTR  144          // padded stage row stride (bytes), conflict-free
#define WSTAGE (RW * XSTR) // per-warp stage (hi plane only) = 2304

__device__ __forceinline__ uint32_t s2u(const void* p) {
    uint32_t a;
    asm("{ .reg .u64 t; cvta.to.shared.u64 t, %1; cvt.u32.u64 %0, t; }"
        : "=r"(a) : "l"(p));
    return a;
}
// split-fp16: (x0,x1) -> hi pack + residual pack (recurrence path only)
__device__ __forceinline__ void packsplit(uint32_t& hp, uint32_t& lp,
                                          float x0, float x1) {
    asm("cvt.rn.f16x2.f32 %0, %1, %2;" : "=r"(hp) : "f"(x1), "f"(x0));
    float f0, f1;
    asm("{.reg .f16 l, h; mov.b32 {l, h}, %2; cvt.f32.f16 %0, l; cvt.f32.f16 %1, h;}"
        : "=f"(f0), "=f"(f1) : "r"(hp));
    asm("cvt.rn.f16x2.f32 %0, %1, %2;" : "=r"(lp) : "f"(x1 - f1), "f"(x0 - f0));
}
// plain fp16x2 pack (x and weights; residuals dropped)
__device__ __forceinline__ uint32_t packh(float x0, float x1) {
    uint32_t u;
    asm("cvt.rn.f16x2.f32 %0, %1, %2;" : "=r"(u) : "f"(x1), "f"(x0));
    return u;
}
__device__ __forceinline__ void ldsm4(uint32_t& r0, uint32_t& r1, uint32_t& r2,
                                      uint32_t& r3, uint32_t addr) {
    asm volatile("ldmatrix.sync.aligned.m8n8.x4.shared.b16 {%0,%1,%2,%3}, [%4];"
                 : "=r"(r0), "=r"(r1), "=r"(r2), "=r"(r3) : "r"(addr));
}
__device__ __forceinline__ void mma16816(float* c, uint32_t a0, uint32_t a1,
                                         uint32_t a2, uint32_t a3,
                                         uint32_t b0, uint32_t b1) {
    asm volatile(
        "mma.sync.aligned.m16n8k16.row.col.f32.f16.f16.f32 "
        "{%0,%1,%2,%3}, {%4,%5,%6,%7}, {%8,%9}, {%0,%1,%2,%3};"
        : "+f"(c[0]), "+f"(c[1]), "+f"(c[2]), "+f"(c[3])
        : "r"(a0), "r"(a1), "r"(a2), "r"(a3), "r"(b0), "r"(b1));
}
// single-MUFU activations (validated: rel_err unchanged)
__device__ __forceinline__ float tf_(float x) {
    float y;
    asm("tanh.approx.f32 %0, %1;" : "=f"(y) : "f"(x));
    return y;
}
__device__ __forceinline__ float sg_(float x) {
    return fmaf(0.5f, tf_(0.5f * x), 0.5f);
}

__global__ __launch_bounds__(128, 4)
void lstm_mma7_kernel(const float* __restrict__ x,
                      const float* __restrict__ Wih,   // [64][64]
                      const float* __restrict__ Whh,   // [64][16]
                      const float* __restrict__ bih,
                      const float* __restrict__ bhh,
                      const float* __restrict__ fcw,   // [16]
                      const float* __restrict__ fcb,
                      float* __restrict__ out,
                      int batch)
{
    __shared__ __align__(16) char  s_x[NWARP * WSTAGE];  // hi plane only: 9KB
    __shared__ __align__(16) uint4 s_bx[4 * 4 * 32];     // Wih frag pairs: 8KB

    const int tid  = threadIdx.x;
    const int lane = tid & 31, warp = tid >> 5;
    const int g = lane >> 2, j = lane & 3;

    // ---- pre-pack Wih B-fragment PAIRS into smem (warp 0; lane-indexed,
    //      identical across warps). uint4 = frags for (nt=2p, nt=2p+1). ----
    if (warp == 0) {
#pragma unroll
        for (int ks = 0; ks < 4; ks++)
#pragma unroll
            for (int p = 0; p < 4; p++) {
                const float2* p0 =
                    (const float2*)(Wih + (16 * p + g) * INS + 16 * ks + 2 * j);
                const float2* p1 =
                    (const float2*)(Wih + (16 * p + 8 + g) * INS + 16 * ks + 2 * j);
                float2 a0 = __ldg(p0), a1 = __ldg(p0 + 4);
                float2 b0 = __ldg(p1), b1 = __ldg(p1 + 4);
                s_bx[(ks * 4 + p) * 32 + lane] =
                    make_uint4(packh(a0.x, a0.y), packh(a1.x, a1.y),
                               packh(b0.x, b0.y), packh(b1.x, b1.y));
            }
    }

    // ---- constants in registers: bias (fp32) + Whh frags (fp16) ----
    float2 BiasR[8];
    uint32_t Bhh[8][2];
#pragma unroll
    for (int nt = 0; nt < 8; nt++) {
        int i0 = nt * 8 + 2 * j;
        BiasR[nt] = make_float2(__ldg(bih + i0)     + __ldg(bhh + i0),
                                __ldg(bih + i0 + 1) + __ldg(bhh + i0 + 1));
        const float2* p = (const float2*)(Whh + (8 * nt + g) * HID + 2 * j);
        float2 w0 = __ldg(p);
        float2 w1 = __ldg(p + 4);
        Bhh[nt][0] = packh(w0.x, w0.y);
        Bhh[nt][1] = packh(w1.x, w1.y);
    }
    __syncthreads();

    int rowbase = blockIdx.x * TILE_B + warp * RW;
    if (rowbase + RW > batch) rowbase = batch >= RW ? batch - RW : 0;

    // ---- coalesced x staging: lanes 0-15 = even rows, 16-31 = odd rows ----
    const int half = lane >> 4, q = lane & 15;
    const float* xb = x + (size_t)(rowbase + half) * (SEQT * INS) + q * 4;
    char* hs = s_x + warp * WSTAGE + half * XSTR + q * 8;

    // ldmatrix fragment addresses
    const int mrow = lane & 7, msel = lane >> 3;
    const uint32_t smb = s2u(s_x);
    const uint32_t a_hi = smb + warp * WSTAGE +
        ((msel & 1) * 8 + mrow) * XSTR + (msel >> 1) * 16;
    const uint4* bxl = s_bx + lane;

    // state: h/c [row-half rh][unit uu]; units {2j,2j+1,8+2j,8+2j+1}
    float h[2][4], c[2][4];
#pragma unroll
    for (int rh = 0; rh < 2; rh++)
#pragma unroll
        for (int u = 0; u < 4; u++) { h[rh][u] = 0.f; c[rh][u] = 0.f; }

    // ---- register-carried x prefetch (software pipeline over t) ----
    float4 xf[8];
#pragma unroll
    for (int i = 0; i < 8; i++)
        xf[i] = __ldg((const float4*)(xb + i * (2 * SEQT * INS)));

#pragma unroll 1
    for (int t = 0; t < SEQT; t++) {
        // ---- 1. pack carried x to fp16 + stage (hi plane only) ----
#pragma unroll
        for (int i = 0; i < 8; i++) {
            uint2 H;
            H.x = packh(xf[i].x, xf[i].y);
            H.y = packh(xf[i].z, xf[i].w);
            *(uint2*)(hs + i * (2 * XSTR)) = H;
        }

        // ---- 2. prefetch next step's x (latency covered by mma below) ----
        {
            const int tn = t + 1 < SEQT ? t + 1 : t;
            const float* xt = xb + tn * INS;
#pragma unroll
            for (int i = 0; i < 8; i++)
                xf[i] = __ldg((const float4*)(xt + i * (2 * SEQT * INS)));
        }

        // ---- 3. acc init from register bias ----
        float acc[8][4];
#pragma unroll
        for (int nt = 0; nt < 8; nt++) {
            acc[nt][0] = BiasR[nt].x; acc[nt][1] = BiasR[nt].y;
            acc[nt][2] = BiasR[nt].x; acc[nt][3] = BiasR[nt].y;
        }

        // ---- 4. recurrence: gates += h @ Whh^T (2-pass split, B in regs) ----
        if (t > 0) {
            uint32_t ah[4], al[4];
            packsplit(ah[0], al[0], h[0][0], h[0][1]);
            packsplit(ah[1], al[1], h[1][0], h[1][1]);
            packsplit(ah[2], al[2], h[0][2], h[0][3]);
            packsplit(ah[3], al[3], h[1][2], h[1][3]);
#pragma unroll
            for (int nt = 0; nt < 8; nt++) {
                mma16816(acc[nt], ah[0], ah[1], ah[2], ah[3],
                         Bhh[nt][0], Bhh[nt][1]);
                mma16816(acc[nt], al[0], al[1], al[2], al[3],
                         Bhh[nt][0], Bhh[nt][1]);
            }
        }
        __syncwarp();

        // ---- 5. x-GEMM: gates += x @ Wih^T (single hi pass, LDS.128 pairs) ----
#pragma unroll
        for (int ks = 0; ks < 4; ks++) {
            uint32_t Ah[4];
            ldsm4(Ah[0], Ah[1], Ah[2], Ah[3], a_hi + ks * 32);
#pragma unroll
            for (int p = 0; p < 4; p++) {
                uint4 bx = bxl[(ks * 4 + p) * 32];        // LDS.128 conflict-free
                mma16816(acc[2 * p],     Ah[0], Ah[1], Ah[2], Ah[3], bx.x, bx.y);
                mma16816(acc[2 * p + 1], Ah[0], Ah[1], Ah[2], Ah[3], bx.z, bx.w);
            }
        }

        // ---- 6. activations + state update ----
        // gate qg of unit uu: nt = 2*qg + (uu>>1), reg = (uu&1) + 2*rh
#pragma unroll
        for (int rh = 0; rh < 2; rh++)
#pragma unroll
            for (int uu = 0; uu < 4; uu++) {
                const int nth = uu >> 1, rg = (uu & 1) + 2 * rh;
                float gi = acc[0 + nth][rg];
                float gf = acc[2 + nth][rg];
                float gg = acc[4 + nth][rg];
                float go = acc[6 + nth][rg];
                float ig = sg_(gi), fg = sg_(gf);
                float g2 = tf_(gg), og = sg_(go);
                float cn = fg * c[rh][uu] + ig * g2;
                c[rh][uu] = cn;
                h[rh][uu] = og * tf_(cn);
            }
        __syncwarp();   // all lanes done with ldsm before next step's STS
    }

    // ---- fc head: reduce over the 4 j-lanes of each row ----
    {
        float2 f0 = __ldg((const float2*)(fcw + 2 * j));
        float2 f1 = __ldg((const float2*)(fcw + 8 + 2 * j));
        float fb = __ldg(fcb);
#pragma unroll
        for (int rh = 0; rh < 2; rh++) {
            float p = h[rh][0] * f0.x + h[rh][1] * f0.y +
                      h[rh][2] * f1.x + h[rh][3] * f1.y;
            p += __shfl_xor_sync(0xffffffffu, p, 1);
            p += __shfl_xor_sync(0xffffffffu, p, 2);
            if (j == 0) {
                int row = rowbase + rh * 8 + g;
                if (row < batch) out[row] = p + fb;
            }
        }
    }
}

extern "C" void kernel_launch(void* const* d_in, const int* in_sizes, int n_in,
                              void* d_out, int out_size)
{
    const float* x   = (const float*)d_in[0];
    const float* Wih = (const float*)d_in[1];
    const float* Whh = (const float*)d_in[2];
    const float* bih = (const float*)d_in[3];
    const float* bhh = (const float*)d_in[4];
    const float* fcw = (const float*)d_in[5];
    const float* fcb = (const float*)d_in[6];
    float* out = (float*)d_out;

    int batch = in_sizes[0] / (SEQT * INS);
    int blocks = (batch + TILE_B - 1) / TILE_B;
    lstm_mma7_kernel<<<blocks, 128>>>(x, Wih, Whh, bih, bhh, fcw, fcb,
                                      out, batch);
}

// round 17
// speedup vs baseline: 1.0851x; 1.0851x over previous
#include <cuda_runtime.h>
#include <cstdint>

#define HID   16
#define INS   64
#define SEQT  12
#define RW    16           // rows per warp
#define NWARP 4
#define TILE_B (RW * NWARP)
#define XSTR  144          // padded stage row stride (bytes), conflict-free
#define WSTAGE (RW * XSTR) // per-warp stage (hi plane only) = 2304

__device__ __forceinline__ uint32_t s2u(const void* p) {
    uint32_t a;
    asm("{ .reg .u64 t; cvta.to.shared.u64 t, %1; cvt.u32.u64 %0, t; }"
        : "=r"(a) : "l"(p));
    return a;
}
// split-fp16: (x0,x1) -> hi pack + residual pack (recurrence path only)
__device__ __forceinline__ void packsplit(uint32_t& hp, uint32_t& lp,
                                          float x0, float x1) {
    asm("cvt.rn.f16x2.f32 %0, %1, %2;" : "=r"(hp) : "f"(x1), "f"(x0));
    float f0, f1;
    asm("{.reg .f16 l, h; mov.b32 {l, h}, %2; cvt.f32.f16 %0, l; cvt.f32.f16 %1, h;}"
        : "=f"(f0), "=f"(f1) : "r"(hp));
    asm("cvt.rn.f16x2.f32 %0, %1, %2;" : "=r"(lp) : "f"(x1 - f1), "f"(x0 - f0));
}
// plain fp16x2 pack (x and weights; residuals dropped)
__device__ __forceinline__ uint32_t packh(float x0, float x1) {
    uint32_t u;
    asm("cvt.rn.f16x2.f32 %0, %1, %2;" : "=r"(u) : "f"(x1), "f"(x0));
    return u;
}
__device__ __forceinline__ void ldsm4(uint32_t& r0, uint32_t& r1, uint32_t& r2,
                                      uint32_t& r3, uint32_t addr) {
    asm volatile("ldmatrix.sync.aligned.m8n8.x4.shared.b16 {%0,%1,%2,%3}, [%4];"
                 : "=r"(r0), "=r"(r1), "=r"(r2), "=r"(r3) : "r"(addr));
}
__device__ __forceinline__ void mma16816(float* c, uint32_t a0, uint32_t a1,
                                         uint32_t a2, uint32_t a3,
                                         uint32_t b0, uint32_t b1) {
    asm volatile(
        "mma.sync.aligned.m16n8k16.row.col.f32.f16.f16.f32 "
        "{%0,%1,%2,%3}, {%4,%5,%6,%7}, {%8,%9}, {%0,%1,%2,%3};"
        : "+f"(c[0]), "+f"(c[1]), "+f"(c[2]), "+f"(c[3])
        : "r"(a0), "r"(a1), "r"(a2), "r"(a3), "r"(b0), "r"(b1));
}
// single-MUFU activations (validated: rel_err unchanged)
__device__ __forceinline__ float tf_(float x) {
    float y;
    asm("tanh.approx.f32 %0, %1;" : "=f"(y) : "f"(x));
    return y;
}
__device__ __forceinline__ float sg_(float x) {
    return fmaf(0.5f, tf_(0.5f * x), 0.5f);
}

__global__ __launch_bounds__(128, 5)
void lstm_mma8_kernel(const float* __restrict__ x,
                      const float* __restrict__ Wih,   // [64][64]
                      const float* __restrict__ Whh,   // [64][16]
                      const float* __restrict__ bih,
                      const float* __restrict__ bhh,
                      const float* __restrict__ fcw,   // [16]
                      const float* __restrict__ fcb,
                      float* __restrict__ out,
                      int batch)
{
    __shared__ __align__(16) char  s_x[NWARP * WSTAGE];  // hi plane only: 9KB
    __shared__ __align__(16) uint4 s_bx[4 * 4 * 32];     // Wih frag PAIRS: 8KB
    __shared__ __align__(16) uint2 s_bhh[8 * 32];        // Whh frags/lane: 2KB
    __shared__ __align__(16) float s_bias[64];
    __shared__ __align__(16) float s_fcw[HID];
    __shared__ float s_fcb;

    const int tid  = threadIdx.x;
    const int lane = tid & 31, warp = tid >> 5;
    const int g = lane >> 2, j = lane & 3;

    if (tid < 64)  s_bias[tid] = bih[tid] + bhh[tid];
    if (tid < HID) s_fcw[tid]  = fcw[tid];
    if (tid == 0)  s_fcb       = fcb[0];

    // ---- pre-pack W fragments (hi plane) into smem; lane-indexed, identical
    //      across warps. warp 0: Wih pairs (uint4 = frags for nt=2p, 2p+1);
    //      warp 1: Whh. ----
    if (warp == 0) {
#pragma unroll
        for (int ks = 0; ks < 4; ks++)
#pragma unroll
            for (int p = 0; p < 4; p++) {
                const float2* p0 =
                    (const float2*)(Wih + (16 * p + g) * INS + 16 * ks + 2 * j);
                const float2* p1 =
                    (const float2*)(Wih + (16 * p + 8 + g) * INS + 16 * ks + 2 * j);
                float2 a0 = __ldg(p0), a1 = __ldg(p0 + 4);
                float2 b0 = __ldg(p1), b1 = __ldg(p1 + 4);
                s_bx[(ks * 4 + p) * 32 + lane] =
                    make_uint4(packh(a0.x, a0.y), packh(a1.x, a1.y),
                               packh(b0.x, b0.y), packh(b1.x, b1.y));
            }
    } else if (warp == 1) {
#pragma unroll
        for (int nt = 0; nt < 8; nt++) {
            const float2* p = (const float2*)(Whh + (8 * nt + g) * HID + 2 * j);
            float2 w0 = __ldg(p);
            float2 w1 = __ldg(p + 4);
            s_bhh[nt * 32 + lane] =
                make_uint2(packh(w0.x, w0.y), packh(w1.x, w1.y));
        }
    }
    __syncthreads();

    int rowbase = blockIdx.x * TILE_B + warp * RW;
    if (rowbase + RW > batch) rowbase = batch >= RW ? batch - RW : 0;

    // ---- coalesced x staging: lanes 0-15 = even rows, 16-31 = odd rows ----
    const int half = lane >> 4, q = lane & 15;
    const float* xb = x + (size_t)(rowbase + half) * (SEQT * INS) + q * 4;
    char* hs = s_x + warp * WSTAGE + half * XSTR + q * 8;

    // ldmatrix fragment addresses
    const int mrow = lane & 7, msel = lane >> 3;
    const uint32_t smb = s2u(s_x);
    const uint32_t a_hi = smb + warp * WSTAGE +
        ((msel & 1) * 8 + mrow) * XSTR + (msel >> 1) * 16;
    const uint4* bxl  = s_bx  + lane;
    const uint2* bhhl = s_bhh + lane;

    // state: h/c [row-half rh][unit uu]; units {2j,2j+1,8+2j,8+2j+1}
    float h[2][4], c[2][4];
#pragma unroll
    for (int rh = 0; rh < 2; rh++)
#pragma unroll
        for (int u = 0; u < 4; u++) { h[rh][u] = 0.f; c[rh][u] = 0.f; }

    // ---- register-carried x prefetch (software pipeline over t) ----
    float4 xf[8];
#pragma unroll
    for (int i = 0; i < 8; i++)
        xf[i] = __ldg((const float4*)(xb + i * (2 * SEQT * INS)));

#pragma unroll 1
    for (int t = 0; t < SEQT; t++) {
        // ---- 1. pack carried x to fp16 + stage (hi plane only) ----
#pragma unroll
        for (int i = 0; i < 8; i++) {
            uint2 H;
            H.x = packh(xf[i].x, xf[i].y);
            H.y = packh(xf[i].z, xf[i].w);
            *(uint2*)(hs + i * (2 * XSTR)) = H;
        }

        // ---- 2. prefetch next step's x (latency covered by mma below) ----
        {
            const int tn = t + 1 < SEQT ? t + 1 : t;
            const float* xt = xb + tn * INS;
#pragma unroll
            for (int i = 0; i < 8; i++)
                xf[i] = __ldg((const float4*)(xt + i * (2 * SEQT * INS)));
        }

        // ---- 3. acc init from bias (smem) ----
        float acc[8][4];
#pragma unroll
        for (int nt = 0; nt < 8; nt++) {
            float2 bv = *(const float2*)(s_bias + 8 * nt + 2 * j);
            acc[nt][0] = bv.x; acc[nt][1] = bv.y;
            acc[nt][2] = bv.x; acc[nt][3] = bv.y;
        }

        // ---- 4. recurrence: gates += h @ Whh^T (2-pass split, B from smem) ----
        if (t > 0) {
            uint32_t ah[4], al[4];
            packsplit(ah[0], al[0], h[0][0], h[0][1]);
            packsplit(ah[1], al[1], h[1][0], h[1][1]);
            packsplit(ah[2], al[2], h[0][2], h[0][3]);
            packsplit(ah[3], al[3], h[1][2], h[1][3]);
#pragma unroll
            for (int nt = 0; nt < 8; nt++) {
                uint2 bh = bhhl[nt * 32];
                mma16816(acc[nt], ah[0], ah[1], ah[2], ah[3], bh.x, bh.y);
                mma16816(acc[nt], al[0], al[1], al[2], al[3], bh.x, bh.y);
            }
        }
        __syncwarp();

        // ---- 5. x-GEMM: gates += x @ Wih^T (single hi pass, LDS.128 pairs) ----
#pragma unroll
        for (int ks = 0; ks < 4; ks++) {
            uint32_t Ah[4];
            ldsm4(Ah[0], Ah[1], Ah[2], Ah[3], a_hi + ks * 32);
#pragma unroll
            for (int p = 0; p < 4; p++) {
                uint4 bx = bxl[(ks * 4 + p) * 32];        // one LDS.128 / 2 tiles
                mma16816(acc[2 * p],     Ah[0], Ah[1], Ah[2], Ah[3], bx.x, bx.y);
                mma16816(acc[2 * p + 1], Ah[0], Ah[1], Ah[2], Ah[3], bx.z, bx.w);
            }
        }

        // ---- 6. activations + state update ----
        // gate qg of unit uu: nt = 2*qg + (uu>>1), reg = (uu&1) + 2*rh
#pragma unroll
        for (int rh = 0; rh < 2; rh++)
#pragma unroll
            for (int uu = 0; uu < 4; uu++) {
                const int nth = uu >> 1, rg = (uu & 1) + 2 * rh;
                float gi = acc[0 + nth][rg];
                float gf = acc[2 + nth][rg];
                float gg = acc[4 + nth][rg];
                float go = acc[6 + nth][rg];
                float ig = sg_(gi), fg = sg_(gf);
                float g2 = tf_(gg), og = sg_(go);
                float cn = fg * c[rh][uu] + ig * g2;
                c[rh][uu] = cn;
                h[rh][uu] = og * tf_(cn);
            }
        __syncwarp();   // all lanes done with ldsm before next step's STS
    }

    // ---- fc head: reduce over the 4 j-lanes of each row ----
    {
        float2 f0 = *(const float2*)(s_fcw + 2 * j);
        float2 f1 = *(const float2*)(s_fcw + 8 + 2 * j);
        float fb = s_fcb;
#pragma unroll
        for (int rh = 0; rh < 2; rh++) {
            float p = h[rh][0] * f0.x + h[rh][1] * f0.y +
                      h[rh][2] * f1.x + h[rh][3] * f1.y;
            p += __shfl_xor_sync(0xffffffffu, p, 1);
            p += __shfl_xor_sync(0xffffffffu, p, 2);
            if (j == 0) {
                int row = rowbase + rh * 8 + g;
                if (row < batch) out[row] = p + fb;
            }
        }
    }
}

extern "C" void kernel_launch(void* const* d_in, const int* in_sizes, int n_in,
                              void* d_out, int out_size)
{
    const float* x   = (const float*)d_in[0];
    const float* Wih = (const float*)d_in[1];
    const float* Whh = (const float*)d_in[2];
    const float* bih = (const float*)d_in[3];
    const float* bhh = (const float*)d_in[4];
    const float* fcw = (const float*)d_in[5];
    const float* fcb = (const float*)d_in[6];
    float* out = (float*)d_out;

    int batch = in_sizes[0] / (SEQT * INS);
    int blocks = (batch + TILE_B - 1) / TILE_B;
    lstm_mma8_kernel<<<blocks, 128>>>(x, Wih, Whh, bih, bhh, fcw, fcb,
                                      out, batch);
}